// round 1
// baseline (speedup 1.0000x reference)
#include <cuda_runtime.h>

#define B_  256
#define T_  4096
#define I_  63
#define H_  50
#define FC_ 64

// 256*4096*50 fp32 scratch for the precomputed input projection (~210 MB).
__device__ float g_xz[(size_t)B_ * T_ * H_];

// ---------- packed f32x2 helpers (FFMA2 path, sm_103a) ----------
__device__ __forceinline__ unsigned long long pk2(float a, float b) {
    unsigned long long r;
    asm("mov.b64 %0,{%1,%2};" : "=l"(r) : "f"(a), "f"(b));
    return r;
}
__device__ __forceinline__ unsigned long long fma2(unsigned long long a,
                                                   unsigned long long b,
                                                   unsigned long long c) {
    unsigned long long d;
    asm("fma.rn.f32x2 %0,%1,%2,%3;" : "=l"(d) : "l"(a), "l"(b), "l"(c));
    return d;
}
__device__ __forceinline__ float2 up2(unsigned long long v) {
    float2 r;
    asm("mov.b64 {%0,%1},%2;" : "=f"(r.x), "=f"(r.y) : "l"(v));
    return r;
}

// ================= Kernel A: xz[b,t,:] = x[b,t,:] @ W_ih^T + b_ih + b_hh ====
// One thread computes 2 rows (R=2) so the shared W load is amortized; packed
// f32x2 FMAs over the 25 output pairs (H=50).
__global__ void __launch_bounds__(128) inproj_kernel(
    const float* __restrict__ x,
    const float* __restrict__ W_ih,
    const float* __restrict__ b_ih,
    const float* __restrict__ b_hh)
{
    __shared__ __align__(8) float Wsh[I_ * H_];   // Wsh[i*50 + j] = W_ih[j][i]
    __shared__ __align__(8) float bsh[H_];

    const int tid = threadIdx.x;
    for (int idx = tid; idx < I_ * H_; idx += blockDim.x) {
        int i = idx / H_, j = idx % H_;
        Wsh[idx] = W_ih[j * I_ + i];
    }
    for (int j = tid; j < H_; j += blockDim.x) bsh[j] = b_ih[j] + b_hh[j];
    __syncthreads();

    const size_t row0 = ((size_t)blockIdx.x * blockDim.x + tid) * 2;
    const float* xr0 = x + row0 * I_;
    const float* xr1 = xr0 + I_;

    unsigned long long acc0[25], acc1[25];
    const float2* bp = (const float2*)bsh;
#pragma unroll
    for (int j2 = 0; j2 < 25; j2++) {
        float2 bv = bp[j2];
        acc0[j2] = pk2(bv.x, bv.y);
        acc1[j2] = acc0[j2];
    }

#pragma unroll 7
    for (int i = 0; i < I_; i++) {
        float xv0 = __ldg(xr0 + i);
        float xv1 = __ldg(xr1 + i);
        unsigned long long x0d = pk2(xv0, xv0);
        unsigned long long x1d = pk2(xv1, xv1);
        const float2* wrow = (const float2*)(Wsh + i * H_);
#pragma unroll
        for (int j2 = 0; j2 < 25; j2++) {
            unsigned long long w = *(const unsigned long long*)(wrow + j2);
            acc0[j2] = fma2(w, x0d, acc0[j2]);
            acc1[j2] = fma2(w, x1d, acc1[j2]);
        }
    }

    float2* o0 = (float2*)(g_xz + row0 * H_);
    float2* o1 = (float2*)(g_xz + (row0 + 1) * H_);
#pragma unroll
    for (int j2 = 0; j2 < 25; j2++) {
        o0[j2] = up2(acc0[j2]);
        o1[j2] = up2(acc1[j2]);
    }
}

// ============ Kernel B: tanh recurrence (one warp per batch row) + head =====
__global__ void __launch_bounds__(64) rnn_kernel(
    const float* __restrict__ Whh,
    const float* __restrict__ W1, const float* __restrict__ b1,
    const float* __restrict__ W2, const float* __restrict__ b2,
    float* __restrict__ out)
{
    const int warp = threadIdx.x >> 5;
    const int lane = threadIdx.x & 31;
    const int b    = blockIdx.x * 2 + warp;
    const float* xz = g_xz + (size_t)b * T_ * H_;

    const int  r1 = lane + 32;
    const bool hi = (r1 < H_);   // lanes 0..17 own a second hidden unit

    // W_hh rows for this lane's two outputs, register-resident.
    float w0[H_], w1[H_];
#pragma unroll
    for (int k = 0; k < H_; k++) {
        w0[k] = __ldg(Whh + lane * H_ + k);
        w1[k] = hi ? __ldg(Whh + r1 * H_ + k) : 0.0f;
    }

    float h_lo = 0.0f, h_hi = 0.0f;

    // depth-4 xz prefetch ring
    float xl[4], xh[4];
#pragma unroll
    for (int u = 0; u < 4; u++) {
        xl[u] = xz[u * H_ + lane];
        xh[u] = hi ? xz[u * H_ + r1] : 0.0f;
    }

    for (int t = 0; t < T_; t += 4) {
#pragma unroll
        for (int u = 0; u < 4; u++) {
            float a0 = xl[u], a1 = xh[u];
            float a0b = 0.f, a1b = 0.f, a0c = 0.f, a1c = 0.f, a0d = 0.f, a1d = 0.f;

            int tp = t + u + 4;
            if (tp < T_) {
                xl[u] = xz[(size_t)tp * H_ + lane];
                xh[u] = hi ? xz[(size_t)tp * H_ + r1] : 0.0f;
            }

#pragma unroll
            for (int k = 0; k < 32; k += 4) {
                float h0 = __shfl_sync(0xffffffffu, h_lo, k);
                float h1 = __shfl_sync(0xffffffffu, h_lo, k + 1);
                float h2 = __shfl_sync(0xffffffffu, h_lo, k + 2);
                float h3 = __shfl_sync(0xffffffffu, h_lo, k + 3);
                a0  += h0 * w0[k];     a1  += h0 * w1[k];
                a0b += h1 * w0[k + 1]; a1b += h1 * w1[k + 1];
                a0c += h2 * w0[k + 2]; a1c += h2 * w1[k + 2];
                a0d += h3 * w0[k + 3]; a1d += h3 * w1[k + 3];
            }
#pragma unroll
            for (int k = 32; k < 48; k += 4) {
                float h0 = __shfl_sync(0xffffffffu, h_hi, k - 32);
                float h1 = __shfl_sync(0xffffffffu, h_hi, k - 31);
                float h2 = __shfl_sync(0xffffffffu, h_hi, k - 30);
                float h3 = __shfl_sync(0xffffffffu, h_hi, k - 29);
                a0  += h0 * w0[k];     a1  += h0 * w1[k];
                a0b += h1 * w0[k + 1]; a1b += h1 * w1[k + 1];
                a0c += h2 * w0[k + 2]; a1c += h2 * w1[k + 2];
                a0d += h3 * w0[k + 3]; a1d += h3 * w1[k + 3];
            }
            {   // k = 48, 49
                float h0 = __shfl_sync(0xffffffffu, h_hi, 16);
                float h1 = __shfl_sync(0xffffffffu, h_hi, 17);
                a0  += h0 * w0[48]; a1  += h0 * w1[48];
                a0b += h1 * w0[49]; a1b += h1 * w1[49];
            }
            h_lo = tanhf((a0 + a0b) + (a0c + a0d));
            h_hi = tanhf((a1 + a1b) + (a1c + a1d));
        }
    }

    // ---------- MLP head + argmax (negligible cost, once per row) ----------
    __shared__ float sh[2][H_];
    sh[warp][lane] = h_lo;          // rows 0..31
    if (hi) sh[warp][r1] = h_hi;    // rows 32..49
    __syncwarp();

    float fc0 = __ldg(b1 + lane);
    float fc1 = __ldg(b1 + lane + 32);
#pragma unroll
    for (int k = 0; k < H_; k++) {
        float hv = sh[warp][k];
        fc0 += hv * __ldg(W1 + lane * H_ + k);
        fc1 += hv * __ldg(W1 + (lane + 32) * H_ + k);
    }
    fc0 = fmaxf(fc0, 0.0f);
    fc1 = fmaxf(fc1, 0.0f);

    float p0 = fc0 * __ldg(W2 + lane)       + fc1 * __ldg(W2 + lane + 32);
    float p1 = fc0 * __ldg(W2 + FC_ + lane) + fc1 * __ldg(W2 + FC_ + lane + 32);
#pragma unroll
    for (int off = 16; off > 0; off >>= 1) {
        p0 += __shfl_xor_sync(0xffffffffu, p0, off);
        p1 += __shfl_xor_sync(0xffffffffu, p1, off);
    }
    if (lane == 0) {
        p0 += __ldg(b2);
        p1 += __ldg(b2 + 1);
        out[b] = (p1 > p0) ? 1.0f : 0.0f;   // argmax; softmax is monotone
    }
}

extern "C" void kernel_launch(void* const* d_in, const int* in_sizes, int n_in,
                              void* d_out, int out_size)
{
    const float* x    = (const float*)d_in[0];
    const float* W_ih = (const float*)d_in[1];
    const float* b_ih = (const float*)d_in[2];
    const float* W_hh = (const float*)d_in[3];
    const float* b_hh = (const float*)d_in[4];
    const float* W1   = (const float*)d_in[5];
    const float* b1   = (const float*)d_in[6];
    const float* W2   = (const float*)d_in[7];
    const float* b2   = (const float*)d_in[8];
    float* out = (float*)d_out;

    // Phase 1: input projection, 2 rows/thread
    const int rows = B_ * T_;                 // 1,048,576
    const int threads = 128;
    const int blocks = rows / (threads * 2);  // 4096
    inproj_kernel<<<blocks, threads>>>(x, W_ih, b_ih, b_hh);

    // Phase 2: recurrence + head, one warp per batch row
    rnn_kernel<<<B_ / 2, 64>>>(W_hh, W1, b1, W2, b2, out);
}

// round 2
// speedup vs baseline: 1.2536x; 1.2536x over previous
#include <cuda_runtime.h>

#define B_  256
#define T_  4096
#define I_  63
#define H_  50
#define FC_ 64

#define APPROX_END 4032   // last 64 steps use exact tanhf (error washout)

// 256*4096*50 fp32 scratch for the precomputed input projection (~210 MB).
__device__ float g_xz[(size_t)B_ * T_ * H_];

// ---------- packed f32x2 helpers (FFMA2 path, sm_103a) ----------
__device__ __forceinline__ unsigned long long pk2(float a, float b) {
    unsigned long long r;
    asm("mov.b64 %0,{%1,%2};" : "=l"(r) : "f"(a), "f"(b));
    return r;
}
__device__ __forceinline__ unsigned long long fma2(unsigned long long a,
                                                   unsigned long long b,
                                                   unsigned long long c) {
    unsigned long long d;
    asm("fma.rn.f32x2 %0,%1,%2,%3;" : "=l"(d) : "l"(a), "l"(b), "l"(c));
    return d;
}
__device__ __forceinline__ float2 up2(unsigned long long v) {
    float2 r;
    asm("mov.b64 {%0,%1},%2;" : "=f"(r.x), "=f"(r.y) : "l"(v));
    return r;
}
__device__ __forceinline__ float tanh_ap(float x) {
    float y;
    asm("tanh.approx.f32 %0,%1;" : "=f"(y) : "f"(x));
    return y;
}

// ================= Kernel A: xz[b,t,:] = x[b,t,:] @ W_ih^T + b_ih + b_hh ====
__global__ void __launch_bounds__(128) inproj_kernel(
    const float* __restrict__ x,
    const float* __restrict__ W_ih,
    const float* __restrict__ b_ih,
    const float* __restrict__ b_hh)
{
    __shared__ __align__(8) float Wsh[I_ * H_];   // Wsh[i*50 + j] = W_ih[j][i]
    __shared__ __align__(8) float bsh[H_];

    const int tid = threadIdx.x;
    for (int idx = tid; idx < I_ * H_; idx += blockDim.x) {
        int i = idx / H_, j = idx % H_;
        Wsh[idx] = W_ih[j * I_ + i];
    }
    for (int j = tid; j < H_; j += blockDim.x) bsh[j] = b_ih[j] + b_hh[j];
    __syncthreads();

    const size_t row0 = ((size_t)blockIdx.x * blockDim.x + tid) * 2;
    const float* xr0 = x + row0 * I_;
    const float* xr1 = xr0 + I_;

    unsigned long long acc0[25], acc1[25];
    const float2* bp = (const float2*)bsh;
#pragma unroll
    for (int j2 = 0; j2 < 25; j2++) {
        float2 bv = bp[j2];
        acc0[j2] = pk2(bv.x, bv.y);
        acc1[j2] = acc0[j2];
    }

#pragma unroll 7
    for (int i = 0; i < I_; i++) {
        float xv0 = __ldg(xr0 + i);
        float xv1 = __ldg(xr1 + i);
        unsigned long long x0d = pk2(xv0, xv0);
        unsigned long long x1d = pk2(xv1, xv1);
        const float2* wrow = (const float2*)(Wsh + i * H_);
#pragma unroll
        for (int j2 = 0; j2 < 25; j2++) {
            unsigned long long w = *(const unsigned long long*)(wrow + j2);
            acc0[j2] = fma2(w, x0d, acc0[j2]);
            acc1[j2] = fma2(w, x1d, acc1[j2]);
        }
    }

    float2* o0 = (float2*)(g_xz + row0 * H_);
    float2* o1 = (float2*)(g_xz + (row0 + 1) * H_);
#pragma unroll
    for (int j2 = 0; j2 < 25; j2++) {
        o0[j2] = up2(acc0[j2]);
        o1[j2] = up2(acc1[j2]);
    }
}

// ============ Kernel B: tanh recurrence, one warp per batch row + head ======
// Lane L (< 25) owns outputs j0=2L, j1=2L+1. h kept in double-buffered smem
// as packed f32x2 pairs; matvec is k-packed FFMA2 with natural h pairs.
__global__ void __launch_bounds__(32) rnn_kernel(
    const float* __restrict__ Whh,
    const float* __restrict__ W1, const float* __restrict__ b1,
    const float* __restrict__ W2, const float* __restrict__ b2,
    float* __restrict__ out)
{
    __shared__ __align__(16) unsigned long long hbuf[2][25];

    const int lane = threadIdx.x & 31;
    const int b    = blockIdx.x;
    const bool act = (lane < 25);
    const int  Lc  = act ? lane : 24;

    // packed W_hh rows for this lane's two outputs (k-major float2 pairs)
    unsigned long long w0p[25], w1p[25];
    const float* r0 = Whh + (2 * Lc) * H_;
    const float* r1 = r0 + H_;
#pragma unroll
    for (int k2 = 0; k2 < 25; k2++) {
        w0p[k2] = pk2(__ldg(r0 + 2 * k2), __ldg(r0 + 2 * k2 + 1));
        w1p[k2] = pk2(__ldg(r1 + 2 * k2), __ldg(r1 + 2 * k2 + 1));
    }

    if (act) hbuf[0][Lc] = 0ull;
    __syncwarp();

    const float* xzp = g_xz + (size_t)b * T_ * H_ + 2 * Lc;

    // depth-4 prefetch ring (static indices only — no spills)
    float2 xr[4];
#pragma unroll
    for (int u = 0; u < 4; u++) xr[u] = *(const float2*)(xzp + u * H_);

    const unsigned long long Z64 = pk2(0.0f, 0.0f);

#define RNN_STEP(UU, EXACTF) do {                                              \
    const int cb_ = (UU) & 1, nb_ = cb_ ^ 1;                                   \
    float2 xv = xr[UU];                                                        \
    { int tp = t + (UU) + 4;                                                   \
      if (tp < T_) xr[UU] = *(const float2*)(xzp + (size_t)tp * H_); }         \
    unsigned long long acc0a = Z64, acc0b = Z64, acc1a = Z64, acc1b = Z64;     \
    _Pragma("unroll")                                                          \
    for (int k2 = 0; k2 < 25; k2++) {                                          \
        unsigned long long hk = hbuf[cb_][k2];                                 \
        if (k2 & 1) { acc0b = fma2(hk, w0p[k2], acc0b);                        \
                      acc1b = fma2(hk, w1p[k2], acc1b); }                      \
        else        { acc0a = fma2(hk, w0p[k2], acc0a);                        \
                      acc1a = fma2(hk, w1p[k2], acc1a); }                      \
    }                                                                          \
    float2 s0a = up2(acc0a), s0b = up2(acc0b);                                 \
    float2 s1a = up2(acc1a), s1b = up2(acc1b);                                 \
    float a0 = ((s0a.x + s0a.y) + (s0b.x + s0b.y)) + xv.x;                     \
    float a1 = ((s1a.x + s1a.y) + (s1b.x + s1b.y)) + xv.y;                     \
    float h0, h1;                                                              \
    if (EXACTF) { h0 = tanhf(a0);    h1 = tanhf(a1);    }                      \
    else        { h0 = tanh_ap(a0);  h1 = tanh_ap(a1);  }                      \
    if (act) hbuf[nb_][Lc] = pk2(h0, h1);                                      \
    __syncwarp();                                                              \
} while (0)

    for (int t = 0; t < APPROX_END; t += 4) {
        RNN_STEP(0, false); RNN_STEP(1, false);
        RNN_STEP(2, false); RNN_STEP(3, false);
    }
    for (int t = APPROX_END; t < T_; t += 4) {
        RNN_STEP(0, true); RNN_STEP(1, true);
        RNN_STEP(2, true); RNN_STEP(3, true);
    }
#undef RNN_STEP

    // ---------- MLP head + argmax (final h lives in hbuf[0]) ----------
    const float* hf = (const float*)hbuf[0];
    float fc0 = __ldg(b1 + lane);
    float fc1 = __ldg(b1 + lane + 32);
#pragma unroll
    for (int k = 0; k < H_; k++) {
        float hv = hf[k];
        fc0 += hv * __ldg(W1 + lane * H_ + k);
        fc1 += hv * __ldg(W1 + (lane + 32) * H_ + k);
    }
    fc0 = fmaxf(fc0, 0.0f);
    fc1 = fmaxf(fc1, 0.0f);

    float p0 = fc0 * __ldg(W2 + lane)       + fc1 * __ldg(W2 + lane + 32);
    float p1 = fc0 * __ldg(W2 + FC_ + lane) + fc1 * __ldg(W2 + FC_ + lane + 32);
#pragma unroll
    for (int off = 16; off > 0; off >>= 1) {
        p0 += __shfl_xor_sync(0xffffffffu, p0, off);
        p1 += __shfl_xor_sync(0xffffffffu, p1, off);
    }
    if (lane == 0) {
        p0 += __ldg(b2);
        p1 += __ldg(b2 + 1);
        out[b] = (p1 > p0) ? 1.0f : 0.0f;   // argmax; softmax is monotone
    }
}

extern "C" void kernel_launch(void* const* d_in, const int* in_sizes, int n_in,
                              void* d_out, int out_size)
{
    const float* x    = (const float*)d_in[0];
    const float* W_ih = (const float*)d_in[1];
    const float* b_ih = (const float*)d_in[2];
    const float* W_hh = (const float*)d_in[3];
    const float* b_hh = (const float*)d_in[4];
    const float* W1   = (const float*)d_in[5];
    const float* b1   = (const float*)d_in[6];
    const float* W2   = (const float*)d_in[7];
    const float* b2   = (const float*)d_in[8];
    float* out = (float*)d_out;

    // Phase 1: input projection, 2 rows/thread
    const int rows = B_ * T_;                 // 1,048,576
    const int threads = 128;
    const int blocks = rows / (threads * 2);  // 4096
    inproj_kernel<<<blocks, threads>>>(x, W_ih, b_ih, b_hh);

    // Phase 2: recurrence + head, one warp per batch row
    rnn_kernel<<<B_, 32>>>(W_hh, W1, b1, W2, b2, out);
}

// round 3
// speedup vs baseline: 1.2961x; 1.0339x over previous
#include <cuda_runtime.h>

#define B_  256
#define T_  4096
#define I_  63
#define H_  50
#define FC_ 64

#define APPROX_END 4032   // last 64 steps use exact tanhf (error washout)

// input-projection scratch, padded so the depth-4 prefetch ring never branches
__device__ float g_xz[(size_t)B_ * T_ * H_ + 256];

// ---------- packed f32x2 helpers (FFMA2 path, sm_103a) ----------
__device__ __forceinline__ unsigned long long pk2(float a, float b) {
    unsigned long long r;
    asm("mov.b64 %0,{%1,%2};" : "=l"(r) : "f"(a), "f"(b));
    return r;
}
__device__ __forceinline__ unsigned long long fma2(unsigned long long a,
                                                   unsigned long long b,
                                                   unsigned long long c) {
    unsigned long long d;
    asm("fma.rn.f32x2 %0,%1,%2,%3;" : "=l"(d) : "l"(a), "l"(b), "l"(c));
    return d;
}
__device__ __forceinline__ unsigned long long add2(unsigned long long a,
                                                   unsigned long long b) {
    unsigned long long d;
    asm("add.rn.f32x2 %0,%1,%2;" : "=l"(d) : "l"(a), "l"(b));
    return d;
}
__device__ __forceinline__ float2 up2(unsigned long long v) {
    float2 r;
    asm("mov.b64 {%0,%1},%2;" : "=f"(r.x), "=f"(r.y) : "l"(v));
    return r;
}
__device__ __forceinline__ float tanh_ap(float x) {
    float y;
    asm("tanh.approx.f32 %0,%1;" : "=f"(y) : "f"(x));
    return y;
}

// ================= Kernel A: xz[r,:] = x[r,:] @ W_ih^T + b_ih + b_hh ========
// Block = 128 threads, 128 rows. x staged through smem (coalesced in),
// results staged through smem (coalesced out). 1 row/thread compute,
// conflict-free smem reads (stride 63 ≡ 31 mod 32).
__global__ void __launch_bounds__(128) inproj_kernel(
    const float* __restrict__ x,
    const float* __restrict__ W_ih,
    const float* __restrict__ b_ih,
    const float* __restrict__ b_hh)
{
    __shared__ __align__(8) float Wsh[I_ * H_];      // Wsh[i*50+j] = W_ih[j][i]
    __shared__ __align__(8) float bsh[H_];
    __shared__ __align__(8) float xtile[128 * I_];   // 8064 floats (reused for out)

    const int tid = threadIdx.x;
    const size_t row_base = (size_t)blockIdx.x * 128;

    for (int idx = tid; idx < I_ * H_; idx += 128) {
        int i = idx / H_, j = idx % H_;
        Wsh[idx] = W_ih[j * I_ + i];
    }
    for (int j = tid; j < H_; j += 128) bsh[j] = b_ih[j] + b_hh[j];

    // coalesced stage-in of 128 rows of x (8064 contiguous floats)
    const float* xblk = x + row_base * I_;
    for (int idx = tid; idx < 128 * I_; idx += 128) xtile[idx] = xblk[idx];
    __syncthreads();

    unsigned long long acc[25];
    const float2* bp = (const float2*)bsh;
#pragma unroll
    for (int j2 = 0; j2 < 25; j2++) {
        float2 bv = bp[j2];
        acc[j2] = pk2(bv.x, bv.y);
    }

    const float* xr = xtile + tid * I_;
#pragma unroll 9
    for (int i = 0; i < I_; i++) {
        float xv = xr[i];
        unsigned long long xd = pk2(xv, xv);
        const float2* wrow = (const float2*)(Wsh + i * H_);
#pragma unroll
        for (int j2 = 0; j2 < 25; j2++) {
            unsigned long long w = *(const unsigned long long*)(wrow + j2);
            acc[j2] = fma2(w, xd, acc[j2]);
        }
    }
    __syncthreads();   // all x reads done; reuse xtile as output stage

    float2* orow = (float2*)xtile + tid * 25;
#pragma unroll
    for (int j2 = 0; j2 < 25; j2++) orow[j2] = up2(acc[j2]);
    __syncthreads();

    // coalesced stage-out: 128*50 floats = 3200 float2, 25 per thread
    float2* oblk = (float2*)(g_xz + row_base * H_);
    const float2* xt2 = (const float2*)xtile;
#pragma unroll
    for (int u = 0; u < 25; u++) oblk[u * 128 + tid] = xt2[u * 128 + tid];
}

// ============ Kernel B: tanh recurrence, one warp per batch row + head ======
// Lane L (< 25) owns outputs j0=2L, j1=2L+1. h double-buffered in smem as
// packed f32x2; NO per-step branches (padded prefetch, 32-slot hbuf).
__global__ void __launch_bounds__(32) rnn_kernel(
    const float* __restrict__ Whh,
    const float* __restrict__ W1, const float* __restrict__ b1,
    const float* __restrict__ W2, const float* __restrict__ b2,
    float* __restrict__ out)
{
    __shared__ __align__(16) unsigned long long hbuf[2][32];

    const int lane = threadIdx.x & 31;
    const int b    = blockIdx.x;
    const int Lc   = (lane < 25) ? lane : 24;   // weight-row clamp only

    // packed W_hh rows for this lane's two outputs (k-major float2 pairs)
    unsigned long long w0p[25], w1p[25];
    const float* r0 = Whh + (2 * Lc) * H_;
    const float* r1 = r0 + H_;
#pragma unroll
    for (int k2 = 0; k2 < 25; k2++) {
        w0p[k2] = pk2(__ldg(r0 + 2 * k2), __ldg(r0 + 2 * k2 + 1));
        w1p[k2] = pk2(__ldg(r1 + 2 * k2), __ldg(r1 + 2 * k2 + 1));
    }

    hbuf[0][lane] = 0ull;
    __syncwarp();

    const float* xzp = g_xz + (size_t)b * T_ * H_ + 2 * Lc;

    // depth-4 prefetch ring, unconditional (g_xz padded)
    float2 xr[4];
#pragma unroll
    for (int u = 0; u < 4; u++) xr[u] = *(const float2*)(xzp + u * H_);

    const unsigned long long Z64 = pk2(0.0f, 0.0f);

#define RNN_STEP(UU, EXACTF) do {                                              \
    const int cb_ = (UU) & 1, nb_ = cb_ ^ 1;                                   \
    float2 xv = xr[UU];                                                        \
    xr[UU] = *(const float2*)(xzp + (size_t)(t + (UU) + 4) * H_);              \
    unsigned long long acc0a = Z64, acc0b = Z64, acc1a = Z64, acc1b = Z64;     \
    _Pragma("unroll")                                                          \
    for (int k2 = 0; k2 < 25; k2++) {                                          \
        unsigned long long hk = hbuf[cb_][k2];                                 \
        if (k2 & 1) { acc0b = fma2(hk, w0p[k2], acc0b);                        \
                      acc1b = fma2(hk, w1p[k2], acc1b); }                      \
        else        { acc0a = fma2(hk, w0p[k2], acc0a);                        \
                      acc1a = fma2(hk, w1p[k2], acc1a); }                      \
    }                                                                          \
    float2 s0 = up2(add2(acc0a, acc0b));                                       \
    float2 s1 = up2(add2(acc1a, acc1b));                                       \
    float a0 = (s0.x + s0.y) + xv.x;                                           \
    float a1 = (s1.x + s1.y) + xv.y;                                           \
    float h0, h1;                                                              \
    if (EXACTF) { h0 = tanhf(a0);    h1 = tanhf(a1);    }                      \
    else        { h0 = tanh_ap(a0);  h1 = tanh_ap(a1);  }                      \
    hbuf[nb_][lane] = pk2(h0, h1);                                             \
    __syncwarp();                                                              \
} while (0)

    for (int t = 0; t < APPROX_END; t += 4) {
        RNN_STEP(0, false); RNN_STEP(1, false);
        RNN_STEP(2, false); RNN_STEP(3, false);
    }
    for (int t = APPROX_END; t < T_; t += 4) {
        RNN_STEP(0, true); RNN_STEP(1, true);
        RNN_STEP(2, true); RNN_STEP(3, true);
    }
#undef RNN_STEP

    // ---------- MLP head + argmax (final h lives in hbuf[0][0..24]) ----------
    const float* hf = (const float*)hbuf[0];
    float fc0 = __ldg(b1 + lane);
    float fc1 = __ldg(b1 + lane + 32);
#pragma unroll
    for (int k = 0; k < H_; k++) {
        float hv = hf[k];
        fc0 += hv * __ldg(W1 + lane * H_ + k);
        fc1 += hv * __ldg(W1 + (lane + 32) * H_ + k);
    }
    fc0 = fmaxf(fc0, 0.0f);
    fc1 = fmaxf(fc1, 0.0f);

    float p0 = fc0 * __ldg(W2 + lane)       + fc1 * __ldg(W2 + lane + 32);
    float p1 = fc0 * __ldg(W2 + FC_ + lane) + fc1 * __ldg(W2 + FC_ + lane + 32);
#pragma unroll
    for (int off = 16; off > 0; off >>= 1) {
        p0 += __shfl_xor_sync(0xffffffffu, p0, off);
        p1 += __shfl_xor_sync(0xffffffffu, p1, off);
    }
    if (lane == 0) {
        p0 += __ldg(b2);
        p1 += __ldg(b2 + 1);
        out[b] = (p1 > p0) ? 1.0f : 0.0f;   // argmax; softmax is monotone
    }
}

extern "C" void kernel_launch(void* const* d_in, const int* in_sizes, int n_in,
                              void* d_out, int out_size)
{
    const float* x    = (const float*)d_in[0];
    const float* W_ih = (const float*)d_in[1];
    const float* b_ih = (const float*)d_in[2];
    const float* W_hh = (const float*)d_in[3];
    const float* b_hh = (const float*)d_in[4];
    const float* W1   = (const float*)d_in[5];
    const float* b1   = (const float*)d_in[6];
    const float* W2   = (const float*)d_in[7];
    const float* b2   = (const float*)d_in[8];
    float* out = (float*)d_out;

    // Phase 1: input projection, 128 rows per 128-thread block
    inproj_kernel<<<(B_ * T_) / 128, 128>>>(x, W_ih, b_ih, b_hh);

    // Phase 2: recurrence + head, one warp per batch row
    rnn_kernel<<<B_, 32>>>(W_hh, W1, b1, W2, b2, out);
}